// round 16
// baseline (speedup 1.0000x reference)
#include <cuda_runtime.h>

#define BB 2
#define NN 2048
#define DIN 1024
#define DOUT 1024
#define HH 16
#define HD 64

// Scratch (static device allocations — allowed)
__device__ float g_q[BB*HH*NN*HD];
__device__ float g_k[BB*HH*NN*HD];
__device__ float g_v[BB*HH*NN*HD];
__device__ float g_ctx[BB*NN*DOUT];

__device__ __forceinline__ unsigned f2tf32(float f) {
    unsigned r;
    asm("cvt.rna.tf32.f32 %0, %1;" : "=r"(r) : "f"(f));
    return r;
}

__device__ __forceinline__ void mma_tf32(float c[4],
    unsigned a0, unsigned a1, unsigned a2, unsigned a3,
    unsigned b0, unsigned b1)
{
    asm volatile(
        "mma.sync.aligned.m16n8k8.row.col.f32.tf32.tf32.f32 "
        "{%0,%1,%2,%3}, {%4,%5,%6,%7}, {%8,%9}, {%0,%1,%2,%3};"
        : "+f"(c[0]), "+f"(c[1]), "+f"(c[2]), "+f"(c[3])
        : "r"(a0), "r"(a1), "r"(a2), "r"(a3), "r"(b0), "r"(b1));
}

__device__ __forceinline__ void cp16(void* dst, const void* src) {
    unsigned d = (unsigned)__cvta_generic_to_shared(dst);
    asm volatile("cp.async.cg.shared.global [%0], [%1], 16;" :: "r"(d), "l"(src));
}
#define CP_COMMIT() asm volatile("cp.async.commit_group;")
#define CP_WAIT0()  asm volatile("cp.async.wait_group 0;")

// ---------------------------------------------------------------------------
// Fused QKV GEMM — EXACT R13 form (measured best, ~207us): cp.async
// double-buffered, raw fp32 SMEM, tf32 convert at fragment read.
// ---------------------------------------------------------------------------
__global__ __launch_bounds__(256, 2) void qkv_gemm_tc(
    const float* __restrict__ x,
    const float* __restrict__ Wq,
    const float* __restrict__ Wk,
    const float* __restrict__ Wv)
{
    const float* W = (blockIdx.z == 0) ? Wq : (blockIdx.z == 1 ? Wk : Wv);
    float* out = (blockIdx.z == 0) ? g_q : (blockIdx.z == 1 ? g_k : g_v);

    __shared__ float As[2][128][36];
    __shared__ float Bs[2][32][136];

    const int tid  = threadIdx.x;
    const int warp = tid >> 5;
    const int lane = tid & 31;
    const int g    = lane >> 2;
    const int tg   = lane & 3;
    const int wm   = (warp >> 2) * 64;
    const int wn   = (warp & 3) * 32;
    const int bm   = blockIdx.y * 128;
    const int bn   = blockIdx.x * 128;

    int a_r[4], a_c[4], b_r[4], b_c[4];
    #pragma unroll
    for (int s = 0; s < 4; s++) {
        int slot = tid + s * 256;
        a_r[s] = slot >> 3;
        a_c[s] = (slot & 7) << 2;
        b_r[s] = slot >> 5;
        b_c[s] = (slot & 31) << 2;
    }

    float c[16][4];
    #pragma unroll
    for (int t = 0; t < 16; t++)
        #pragma unroll
        for (int i = 0; i < 4; i++) c[t][i] = 0.f;

    #pragma unroll
    for (int s = 0; s < 4; s++) {
        cp16(&As[0][a_r[s]][a_c[s]], &x[(size_t)(bm + a_r[s]) * DIN + a_c[s]]);
        cp16(&Bs[0][b_r[s]][b_c[s]], &W[(size_t)b_r[s] * DOUT + bn + b_c[s]]);
    }
    CP_COMMIT();
    CP_WAIT0();
    __syncthreads();

    const int NKT = DIN / 32;
    for (int kt = 0; kt < NKT; kt++) {
        const int buf = kt & 1;
        if (kt + 1 < NKT) {
            const int k0n = (kt + 1) * 32;
            #pragma unroll
            for (int s = 0; s < 4; s++) {
                cp16(&As[buf ^ 1][a_r[s]][a_c[s]],
                     &x[(size_t)(bm + a_r[s]) * DIN + k0n + a_c[s]]);
                cp16(&Bs[buf ^ 1][b_r[s]][b_c[s]],
                     &W[(size_t)(k0n + b_r[s]) * DOUT + bn + b_c[s]]);
            }
            CP_COMMIT();
        }

        #pragma unroll
        for (int kk = 0; kk < 32; kk += 8) {
            unsigned a[4][4], b[4][2];
            #pragma unroll
            for (int mt = 0; mt < 4; mt++) {
                int row = wm + mt * 16 + g;
                a[mt][0] = f2tf32(As[buf][row    ][kk + tg    ]);
                a[mt][1] = f2tf32(As[buf][row + 8][kk + tg    ]);
                a[mt][2] = f2tf32(As[buf][row    ][kk + tg + 4]);
                a[mt][3] = f2tf32(As[buf][row + 8][kk + tg + 4]);
            }
            #pragma unroll
            for (int nt = 0; nt < 4; nt++) {
                int col = wn + nt * 8 + g;
                b[nt][0] = f2tf32(Bs[buf][kk + tg    ][col]);
                b[nt][1] = f2tf32(Bs[buf][kk + tg + 4][col]);
            }
            #pragma unroll
            for (int mt = 0; mt < 4; mt++)
                #pragma unroll
                for (int nt = 0; nt < 4; nt++)
                    mma_tf32(c[mt * 4 + nt],
                             a[mt][0], a[mt][1], a[mt][2], a[mt][3],
                             b[nt][0], b[nt][1]);
        }

        if (kt + 1 < NKT) CP_WAIT0();
        __syncthreads();
    }

    #pragma unroll
    for (int mt = 0; mt < 4; mt++) {
        #pragma unroll
        for (int nt = 0; nt < 4; nt++) {
            int col = bn + wn + nt * 8 + tg * 2;
            int h_ = col >> 6;
            int d_ = col & 63;
            #pragma unroll
            for (int half = 0; half < 2; half++) {
                int row = bm + wm + mt * 16 + g + half * 8;
                int b_ = row >> 11;
                int n_ = row & 2047;
                float* p = &out[(((size_t)(b_ * HH + h_) * NN) + n_) * HD + d_];
                p[0] = c[mt * 4 + nt][half * 2 + 0];
                p[1] = c[mt * 4 + nt][half * 2 + 1];
            }
        }
    }
}

// ---------------------------------------------------------------------------
// Output GEMM — EXACT R13 form.
// ---------------------------------------------------------------------------
__global__ __launch_bounds__(256, 2) void out_gemm_tc(
    const float* __restrict__ Wo,
    const float* __restrict__ bo,
    float* __restrict__ out)
{
    __shared__ float As[2][128][36];
    __shared__ float Bs[2][32][136];

    const int tid  = threadIdx.x;
    const int warp = tid >> 5;
    const int lane = tid & 31;
    const int g    = lane >> 2;
    const int tg   = lane & 3;
    const int wm   = (warp >> 2) * 64;
    const int wn   = (warp & 3) * 32;
    const int bm   = blockIdx.y * 128;
    const int bn   = blockIdx.x * 128;

    int a_r[4], a_c[4], b_r[4], b_c[4];
    #pragma unroll
    for (int s = 0; s < 4; s++) {
        int slot = tid + s * 256;
        a_r[s] = slot >> 3;
        a_c[s] = (slot & 7) << 2;
        b_r[s] = slot >> 5;
        b_c[s] = (slot & 31) << 2;
    }

    float c[16][4];
    #pragma unroll
    for (int t = 0; t < 16; t++)
        #pragma unroll
        for (int i = 0; i < 4; i++) c[t][i] = 0.f;

    #pragma unroll
    for (int s = 0; s < 4; s++) {
        cp16(&As[0][a_r[s]][a_c[s]], &g_ctx[(size_t)(bm + a_r[s]) * DOUT + a_c[s]]);
        cp16(&Bs[0][b_r[s]][b_c[s]], &Wo[(size_t)b_r[s] * DOUT + bn + b_c[s]]);
    }
    CP_COMMIT();
    CP_WAIT0();
    __syncthreads();

    const int NKT = DOUT / 32;
    for (int kt = 0; kt < NKT; kt++) {
        const int buf = kt & 1;
        if (kt + 1 < NKT) {
            const int k0n = (kt + 1) * 32;
            #pragma unroll
            for (int s = 0; s < 4; s++) {
                cp16(&As[buf ^ 1][a_r[s]][a_c[s]],
                     &g_ctx[(size_t)(bm + a_r[s]) * DOUT + k0n + a_c[s]]);
                cp16(&Bs[buf ^ 1][b_r[s]][b_c[s]],
                     &Wo[(size_t)(k0n + b_r[s]) * DOUT + bn + b_c[s]]);
            }
            CP_COMMIT();
        }

        #pragma unroll
        for (int kk = 0; kk < 32; kk += 8) {
            unsigned a[4][4], b[4][2];
            #pragma unroll
            for (int mt = 0; mt < 4; mt++) {
                int row = wm + mt * 16 + g;
                a[mt][0] = f2tf32(As[buf][row    ][kk + tg    ]);
                a[mt][1] = f2tf32(As[buf][row + 8][kk + tg    ]);
                a[mt][2] = f2tf32(As[buf][row    ][kk + tg + 4]);
                a[mt][3] = f2tf32(As[buf][row + 8][kk + tg + 4]);
            }
            #pragma unroll
            for (int nt = 0; nt < 4; nt++) {
                int col = wn + nt * 8 + g;
                b[nt][0] = f2tf32(Bs[buf][kk + tg    ][col]);
                b[nt][1] = f2tf32(Bs[buf][kk + tg + 4][col]);
            }
            #pragma unroll
            for (int mt = 0; mt < 4; mt++)
                #pragma unroll
                for (int nt = 0; nt < 4; nt++)
                    mma_tf32(c[mt * 4 + nt],
                             a[mt][0], a[mt][1], a[mt][2], a[mt][3],
                             b[nt][0], b[nt][1]);
        }

        if (kt + 1 < NKT) CP_WAIT0();
        __syncthreads();
    }

    #pragma unroll
    for (int mt = 0; mt < 4; mt++) {
        #pragma unroll
        for (int nt = 0; nt < 4; nt++) {
            int col = bn + wn + nt * 8 + tg * 2;
            float b0 = bo[col], b1 = bo[col + 1];
            #pragma unroll
            for (int half = 0; half < 2; half++) {
                int row = bm + wm + mt * 16 + g + half * 8;
                float* p = &out[(size_t)row * DOUT + col];
                p[0] = c[mt * 4 + nt][half * 2 + 0] + b0;
                p[1] = c[mt * 4 + nt][half * 2 + 1] + b1;
            }
        }
    }
}

// ---------------------------------------------------------------------------
// Tensor-core flash attention with VECTORIZED fragment loads.
// Layouts (pitch 68 words throughout, SMEM size unchanged = 113KB, 2 blk/SM):
//   Q, K, P: k-permuted  pA(k) = (k&3)*16 + (k>>2)
//     -> A-frag / K-B-frag uint4 at [row*68 + tg*16 + 4*q4] covers the
//        fragments for kk = 16*q4 (comps 0,1) and kk = 16*q4+8 (comps 2,3),
//        since pA(kk+tg) = tg*16 + kk/4 and pA(kk+tg+4) = tg*16 + kk/4 + 1.
//   V: col-permuted  pV(c) = (c&7)*8 + (c>>3)
//     -> the 4 nt-columns (wn+nt*8+g) are one uint4 at [k*68 + g*8 + wn/8].
// MMA-phase LDS per warp per K-tile: 192 scalar -> 64 LDS.128.
// Q stored ONCE per block; K/V re-stored per tile as 4 scalar STS each
// (amortized against 4x read reduction — the R14 mistake was paying
// permuted-store cost on tiles with only 1x read reuse).
// Math is bit-identical to R13 (same tf32 values, same MMA order):
// rel_err must be exactly 0.0007212442.
// ---------------------------------------------------------------------------
#define QS_OFF 0
#define KS_OFF (128*68)
#define VS_OFF (KS_OFF + 64*68)
#define PS_OFF (VS_OFF + 64*68)
#define RS_OFF (PS_OFF + 128*68)
#define LS_OFF (RS_OFF + 2048)
#define ATTN_SMEM_FLOATS (LS_OFF + 128)
#define ATTN_SMEM_BYTES (ATTN_SMEM_FLOATS * 4)

__global__ __launch_bounds__(256, 2) void attn_tc(
    const float* __restrict__ wp,
    const float* __restrict__ vp)
{
    extern __shared__ float sm[];
    unsigned* Qs = (unsigned*)sm + QS_OFF;
    unsigned* Ks = (unsigned*)sm + KS_OFF;
    unsigned* Vs = (unsigned*)sm + VS_OFF;
    unsigned* Ps = (unsigned*)sm + PS_OFF;
    float*    Rs = sm + RS_OFF;
    float*    Ls = sm + LS_OFF;

    const int qb  = (NN / 128 - 1) - blockIdx.x;   // largest-first
    const int h   = blockIdx.y;
    const int b   = blockIdx.z;
    const int tid = threadIdx.x;
    const int warp = tid >> 5;
    const int lane = tid & 31;
    const int g  = lane >> 2;
    const int tg = lane & 3;
    const int wm = (warp >> 1) * 32;
    const int wn = (warp & 1) * 32;
    const int wq8 = wn >> 3;   // 0 or 4, for V reads
    const int wq4 = wn >> 2;   // 0 or 8, for P writes

    const size_t head_off = (size_t)(b * HH + h) * NN * HD;
    const float* qbase = g_q + head_off;
    const float* kbase = g_k + head_off;
    const float* vbase = g_v + head_off;

    const float wh = wp[h];
    const float vh = vp[h];
    const float c1 = 1.f + __expf(vh);

    for (int i = tid; i < NN; i += 256)
        Rs[i] = c1 / (1.f + __expf(vh - wh * (float)i)) * 0.125f;
    if (tid < 128) Ls[tid] = 0.f;

    // Load Q tile ONCE, k-permuted, pre-converted tf32.
    #pragma unroll
    for (int s = 0; s < 8; s++) {
        int slot = tid + s * 256;
        int r  = slot >> 4;
        int c4 = (slot & 15) << 2;
        float4 v = *(const float4*)&qbase[(size_t)(qb * 128 + r) * HD + c4];
        int base = r * 68 + (c4 >> 2);
        Qs[base     ] = f2tf32(v.x);
        Qs[base + 16] = f2tf32(v.y);
        Qs[base + 32] = f2tf32(v.z);
        Qs[base + 48] = f2tf32(v.w);
    }
    __syncthreads();

    float co[2][4][4];
    #pragma unroll
    for (int mt = 0; mt < 2; mt++)
        #pragma unroll
        for (int nt = 0; nt < 4; nt++)
            #pragma unroll
            for (int i = 0; i < 4; i++) co[mt][nt][i] = 0.f;

    const int ktmax = (qb + 1) * 2;
    for (int kt = 0; kt < ktmax; kt++) {
        const int k0 = kt * 64;

        // Load K (k-permuted) and V (col-permuted) tiles.
        #pragma unroll
        for (int s = 0; s < 4; s++) {
            int slot = tid + s * 256;
            int r  = slot >> 4;
            int c4 = (slot & 15) << 2;
            float4 kv = *(const float4*)&kbase[(size_t)(k0 + r) * HD + c4];
            float4 vv = *(const float4*)&vbase[(size_t)(k0 + r) * HD + c4];
            int kb = r * 68 + (c4 >> 2);
            Ks[kb     ] = f2tf32(kv.x);
            Ks[kb + 16] = f2tf32(kv.y);
            Ks[kb + 32] = f2tf32(kv.z);
            Ks[kb + 48] = f2tf32(kv.w);
            int vb = r * 68 + ((c4 & 7) << 3) + (c4 >> 3);
            Vs[vb     ] = f2tf32(vv.x);
            Vs[vb +  8] = f2tf32(vv.y);
            Vs[vb + 16] = f2tf32(vv.z);
            Vs[vb + 24] = f2tf32(vv.w);
        }
        __syncthreads();

        // ---- S = Q K^T : vectorized fragment loads ----
        float cs[2][4][4];
        #pragma unroll
        for (int mt = 0; mt < 2; mt++)
            #pragma unroll
            for (int nt = 0; nt < 4; nt++)
                #pragma unroll
                for (int i = 0; i < 4; i++) cs[mt][nt][i] = 0.f;

        #pragma unroll
        for (int q4 = 0; q4 < 4; q4++) {
            uint4 aq[2][2], bk[4];
            #pragma unroll
            for (int mt = 0; mt < 2; mt++) {
                int row = wm + mt * 16 + g;
                aq[mt][0] = *(const uint4*)&Qs[row * 68 + tg * 16 + q4 * 4];
                aq[mt][1] = *(const uint4*)&Qs[(row + 8) * 68 + tg * 16 + q4 * 4];
            }
            #pragma unroll
            for (int nt = 0; nt < 4; nt++) {
                int col = wn + nt * 8 + g;
                bk[nt] = *(const uint4*)&Ks[col * 68 + tg * 16 + q4 * 4];
            }
            #pragma unroll
            for (int kh = 0; kh < 2; kh++) {
                const unsigned* b4;
                #pragma unroll
                for (int mt = 0; mt < 2; mt++) {
                    const unsigned* a0p = (const unsigned*)&aq[mt][0];
                    const unsigned* a1p = (const unsigned*)&aq[mt][1];
                    unsigned a0 = a0p[kh * 2    ];
                    unsigned a1 = a1p[kh * 2    ];
                    unsigned a2 = a0p[kh * 2 + 1];
                    unsigned a3 = a1p[kh * 2 + 1];
                    #pragma unroll
                    for (int nt = 0; nt < 4; nt++) {
                        b4 = (const unsigned*)&bk[nt];
                        mma_tf32(cs[mt][nt], a0, a1, a2, a3,
                                 b4[kh * 2], b4[kh * 2 + 1]);
                    }
                }
            }
        }

        // ---- elementwise: relu, gate, exp; P -> SMEM (k-permuted) ----
        float rp[2][2] = {{0.f, 0.f}, {0.f, 0.f}};
        #pragma unroll
        for (int mt = 0; mt < 2; mt++) {
            #pragma unroll
            for (int nt = 0; nt < 4; nt++) {
                #pragma unroll
                for (int i = 0; i < 4; i++) {
                    int half = i >> 1;
                    int row_l = wm + mt * 16 + g + half * 8;
                    int t2 = tg * 2 + (i & 1);
                    int col = wn + nt * 8 + t2;
                    int R = (qb * 128 + row_l) - (k0 + col);
                    float s = fmaxf(cs[mt][nt][i], 0.f);
                    float p = (R >= 0) ? __expf(s * Rs[R]) : 0.f;
                    unsigned pt = f2tf32(p);
                    int pp = ((t2 & 3) << 4) + (t2 >> 2) + wq4 + nt * 2;
                    Ps[row_l * 68 + pp] = pt;
                    rp[mt][half] += __uint_as_float(pt);
                }
            }
        }
        #pragma unroll
        for (int mt = 0; mt < 2; mt++)
            #pragma unroll
            for (int half = 0; half < 2; half++) {
                float v = rp[mt][half];
                v += __shfl_xor_sync(0xffffffff, v, 1);
                v += __shfl_xor_sync(0xffffffff, v, 2);
                if (tg == 0)
                    atomicAdd(&Ls[wm + mt * 16 + g + half * 8], v);
            }
        __syncthreads();

        // ---- O += P V : vectorized fragment loads ----
        #pragma unroll
        for (int q4 = 0; q4 < 4; q4++) {
            uint4 pq[2][2];
            #pragma unroll
            for (int mt = 0; mt < 2; mt++) {
                int row = wm + mt * 16 + g;
                pq[mt][0] = *(const uint4*)&Ps[row * 68 + tg * 16 + q4 * 4];
                pq[mt][1] = *(const uint4*)&Ps[(row + 8) * 68 + tg * 16 + q4 * 4];
            }
            #pragma unroll
            for (int kh = 0; kh < 2; kh++) {
                int kk = q4 * 16 + kh * 8;
                uint4 vv0 = *(const uint4*)&Vs[(kk + tg    ) * 68 + g * 8 + wq8];
                uint4 vv1 = *(const uint4*)&Vs[(kk + tg + 4) * 68 + g * 8 + wq8];
                const unsigned* v0 = (const unsigned*)&vv0;
                const unsigned* v1 = (const unsigned*)&vv1;
                #pragma unroll
                for (int mt = 0; mt < 2; mt++) {
                    const unsigned* a0p = (const unsigned*)&pq[mt][0];
                    const unsigned* a1p = (const unsigned*)&pq[mt][1];
                    unsigned a0 = a0p[kh * 2    ];
                    unsigned a1 = a1p[kh * 2    ];
                    unsigned a2 = a0p[kh * 2 + 1];
                    unsigned a3 = a1p[kh * 2 + 1];
                    #pragma unroll
                    for (int nt = 0; nt < 4; nt++)
                        mma_tf32(co[mt][nt], a0, a1, a2, a3,
                                 v0[nt], v1[nt]);
                }
            }
        }
        __syncthreads();
    }

    #pragma unroll
    for (int mt = 0; mt < 2; mt++) {
        #pragma unroll
        for (int half = 0; half < 2; half++) {
            int row_l = wm + mt * 16 + g + half * 8;
            float inv = 1.f / Ls[row_l];
            int n_ = qb * 128 + row_l;
            float* op = g_ctx + ((size_t)(b * NN + n_) * DOUT) + h * HD;
            #pragma unroll
            for (int nt = 0; nt < 4; nt++) {
                int col = wn + nt * 8 + tg * 2;
                op[col]     = co[mt][nt][half * 2 + 0] * inv;
                op[col + 1] = co[mt][nt][half * 2 + 1] * inv;
            }
        }
    }
}

// ---------------------------------------------------------------------------
extern "C" void kernel_launch(void* const* d_in, const int* in_sizes, int n_in,
                              void* d_out, int out_size)
{
    const float* x  = (const float*)d_in[0];
    const float* Wq = (const float*)d_in[1];
    const float* Wk = (const float*)d_in[2];
    const float* Wv = (const float*)d_in[3];
    const float* Wo = (const float*)d_in[4];
    const float* bo = (const float*)d_in[5];
    const float* w  = (const float*)d_in[6];
    const float* v  = (const float*)d_in[7];
    float* out = (float*)d_out;

    cudaFuncSetAttribute(attn_tc,
        cudaFuncAttributeMaxDynamicSharedMemorySize, ATTN_SMEM_BYTES);

    dim3 g1(DOUT / 128, (BB * NN) / 128, 3);
    qkv_gemm_tc<<<g1, 256>>>(x, Wq, Wk, Wv);

    dim3 g2(NN / 128, HH, BB);
    attn_tc<<<g2, 256, ATTN_SMEM_BYTES>>>(w, v);

    dim3 g3(DOUT / 128, (BB * NN) / 128, 1);
    out_gemm_tc<<<g3, 256>>>(Wo, bo, out);
}

// round 17
// speedup vs baseline: 1.1399x; 1.1399x over previous
#include <cuda_runtime.h>

#define BB 2
#define NN 2048
#define DIN 1024
#define DOUT 1024
#define HH 16
#define HD 64

// Scratch (static device allocations — allowed)
__device__ float g_q[BB*HH*NN*HD];
__device__ float g_k[BB*HH*NN*HD];
__device__ float g_v[BB*HH*NN*HD];
__device__ float g_ctx[BB*NN*DOUT];

__device__ __forceinline__ unsigned f2tf32(float f) {
    unsigned r;
    asm("cvt.rna.tf32.f32 %0, %1;" : "=r"(r) : "f"(f));
    return r;
}

__device__ __forceinline__ void mma_tf32(float c[4],
    unsigned a0, unsigned a1, unsigned a2, unsigned a3,
    unsigned b0, unsigned b1)
{
    asm volatile(
        "mma.sync.aligned.m16n8k8.row.col.f32.tf32.tf32.f32 "
        "{%0,%1,%2,%3}, {%4,%5,%6,%7}, {%8,%9}, {%0,%1,%2,%3};"
        : "+f"(c[0]), "+f"(c[1]), "+f"(c[2]), "+f"(c[3])
        : "r"(a0), "r"(a1), "r"(a2), "r"(a3), "r"(b0), "r"(b1));
}

__device__ __forceinline__ void cp16(void* dst, const void* src) {
    unsigned d = (unsigned)__cvta_generic_to_shared(dst);
    asm volatile("cp.async.cg.shared.global [%0], [%1], 16;" :: "r"(d), "l"(src));
}
#define CP_COMMIT() asm volatile("cp.async.commit_group;")
#define CP_WAIT0()  asm volatile("cp.async.wait_group 0;")

// ---------------------------------------------------------------------------
// Fused QKV GEMM — EXACT R13 form (measured best, ~207us).
// ---------------------------------------------------------------------------
__global__ __launch_bounds__(256, 2) void qkv_gemm_tc(
    const float* __restrict__ x,
    const float* __restrict__ Wq,
    const float* __restrict__ Wk,
    const float* __restrict__ Wv)
{
    const float* W = (blockIdx.z == 0) ? Wq : (blockIdx.z == 1 ? Wk : Wv);
    float* out = (blockIdx.z == 0) ? g_q : (blockIdx.z == 1 ? g_k : g_v);

    __shared__ float As[2][128][36];
    __shared__ float Bs[2][32][136];

    const int tid  = threadIdx.x;
    const int warp = tid >> 5;
    const int lane = tid & 31;
    const int g    = lane >> 2;
    const int tg   = lane & 3;
    const int wm   = (warp >> 2) * 64;
    const int wn   = (warp & 3) * 32;
    const int bm   = blockIdx.y * 128;
    const int bn   = blockIdx.x * 128;

    int a_r[4], a_c[4], b_r[4], b_c[4];
    #pragma unroll
    for (int s = 0; s < 4; s++) {
        int slot = tid + s * 256;
        a_r[s] = slot >> 3;
        a_c[s] = (slot & 7) << 2;
        b_r[s] = slot >> 5;
        b_c[s] = (slot & 31) << 2;
    }

    float c[16][4];
    #pragma unroll
    for (int t = 0; t < 16; t++)
        #pragma unroll
        for (int i = 0; i < 4; i++) c[t][i] = 0.f;

    #pragma unroll
    for (int s = 0; s < 4; s++) {
        cp16(&As[0][a_r[s]][a_c[s]], &x[(size_t)(bm + a_r[s]) * DIN + a_c[s]]);
        cp16(&Bs[0][b_r[s]][b_c[s]], &W[(size_t)b_r[s] * DOUT + bn + b_c[s]]);
    }
    CP_COMMIT();
    CP_WAIT0();
    __syncthreads();

    const int NKT = DIN / 32;
    for (int kt = 0; kt < NKT; kt++) {
        const int buf = kt & 1;
        if (kt + 1 < NKT) {
            const int k0n = (kt + 1) * 32;
            #pragma unroll
            for (int s = 0; s < 4; s++) {
                cp16(&As[buf ^ 1][a_r[s]][a_c[s]],
                     &x[(size_t)(bm + a_r[s]) * DIN + k0n + a_c[s]]);
                cp16(&Bs[buf ^ 1][b_r[s]][b_c[s]],
                     &W[(size_t)(k0n + b_r[s]) * DOUT + bn + b_c[s]]);
            }
            CP_COMMIT();
        }

        #pragma unroll
        for (int kk = 0; kk < 32; kk += 8) {
            unsigned a[4][4], b[4][2];
            #pragma unroll
            for (int mt = 0; mt < 4; mt++) {
                int row = wm + mt * 16 + g;
                a[mt][0] = f2tf32(As[buf][row    ][kk + tg    ]);
                a[mt][1] = f2tf32(As[buf][row + 8][kk + tg    ]);
                a[mt][2] = f2tf32(As[buf][row    ][kk + tg + 4]);
                a[mt][3] = f2tf32(As[buf][row + 8][kk + tg + 4]);
            }
            #pragma unroll
            for (int nt = 0; nt < 4; nt++) {
                int col = wn + nt * 8 + g;
                b[nt][0] = f2tf32(Bs[buf][kk + tg    ][col]);
                b[nt][1] = f2tf32(Bs[buf][kk + tg + 4][col]);
            }
            #pragma unroll
            for (int mt = 0; mt < 4; mt++)
                #pragma unroll
                for (int nt = 0; nt < 4; nt++)
                    mma_tf32(c[mt * 4 + nt],
                             a[mt][0], a[mt][1], a[mt][2], a[mt][3],
                             b[nt][0], b[nt][1]);
        }

        if (kt + 1 < NKT) CP_WAIT0();
        __syncthreads();
    }

    #pragma unroll
    for (int mt = 0; mt < 4; mt++) {
        #pragma unroll
        for (int nt = 0; nt < 4; nt++) {
            int col = bn + wn + nt * 8 + tg * 2;
            int h_ = col >> 6;
            int d_ = col & 63;
            #pragma unroll
            for (int half = 0; half < 2; half++) {
                int row = bm + wm + mt * 16 + g + half * 8;
                int b_ = row >> 11;
                int n_ = row & 2047;
                float* p = &out[(((size_t)(b_ * HH + h_) * NN) + n_) * HD + d_];
                p[0] = c[mt * 4 + nt][half * 2 + 0];
                p[1] = c[mt * 4 + nt][half * 2 + 1];
            }
        }
    }
}

// ---------------------------------------------------------------------------
// Output GEMM — EXACT R13 form.
// ---------------------------------------------------------------------------
__global__ __launch_bounds__(256, 2) void out_gemm_tc(
    const float* __restrict__ Wo,
    const float* __restrict__ bo,
    float* __restrict__ out)
{
    __shared__ float As[2][128][36];
    __shared__ float Bs[2][32][136];

    const int tid  = threadIdx.x;
    const int warp = tid >> 5;
    const int lane = tid & 31;
    const int g    = lane >> 2;
    const int tg   = lane & 3;
    const int wm   = (warp >> 2) * 64;
    const int wn   = (warp & 3) * 32;
    const int bm   = blockIdx.y * 128;
    const int bn   = blockIdx.x * 128;

    int a_r[4], a_c[4], b_r[4], b_c[4];
    #pragma unroll
    for (int s = 0; s < 4; s++) {
        int slot = tid + s * 256;
        a_r[s] = slot >> 3;
        a_c[s] = (slot & 7) << 2;
        b_r[s] = slot >> 5;
        b_c[s] = (slot & 31) << 2;
    }

    float c[16][4];
    #pragma unroll
    for (int t = 0; t < 16; t++)
        #pragma unroll
        for (int i = 0; i < 4; i++) c[t][i] = 0.f;

    #pragma unroll
    for (int s = 0; s < 4; s++) {
        cp16(&As[0][a_r[s]][a_c[s]], &g_ctx[(size_t)(bm + a_r[s]) * DOUT + a_c[s]]);
        cp16(&Bs[0][b_r[s]][b_c[s]], &Wo[(size_t)b_r[s] * DOUT + bn + b_c[s]]);
    }
    CP_COMMIT();
    CP_WAIT0();
    __syncthreads();

    const int NKT = DOUT / 32;
    for (int kt = 0; kt < NKT; kt++) {
        const int buf = kt & 1;
        if (kt + 1 < NKT) {
            const int k0n = (kt + 1) * 32;
            #pragma unroll
            for (int s = 0; s < 4; s++) {
                cp16(&As[buf ^ 1][a_r[s]][a_c[s]],
                     &g_ctx[(size_t)(bm + a_r[s]) * DOUT + k0n + a_c[s]]);
                cp16(&Bs[buf ^ 1][b_r[s]][b_c[s]],
                     &Wo[(size_t)(k0n + b_r[s]) * DOUT + bn + b_c[s]]);
            }
            CP_COMMIT();
        }

        #pragma unroll
        for (int kk = 0; kk < 32; kk += 8) {
            unsigned a[4][4], b[4][2];
            #pragma unroll
            for (int mt = 0; mt < 4; mt++) {
                int row = wm + mt * 16 + g;
                a[mt][0] = f2tf32(As[buf][row    ][kk + tg    ]);
                a[mt][1] = f2tf32(As[buf][row + 8][kk + tg    ]);
                a[mt][2] = f2tf32(As[buf][row    ][kk + tg + 4]);
                a[mt][3] = f2tf32(As[buf][row + 8][kk + tg + 4]);
            }
            #pragma unroll
            for (int nt = 0; nt < 4; nt++) {
                int col = wn + nt * 8 + g;
                b[nt][0] = f2tf32(Bs[buf][kk + tg    ][col]);
                b[nt][1] = f2tf32(Bs[buf][kk + tg + 4][col]);
            }
            #pragma unroll
            for (int mt = 0; mt < 4; mt++)
                #pragma unroll
                for (int nt = 0; nt < 4; nt++)
                    mma_tf32(c[mt * 4 + nt],
                             a[mt][0], a[mt][1], a[mt][2], a[mt][3],
                             b[nt][0], b[nt][1]);
        }

        if (kt + 1 < NKT) CP_WAIT0();
        __syncthreads();
    }

    #pragma unroll
    for (int mt = 0; mt < 4; mt++) {
        #pragma unroll
        for (int nt = 0; nt < 4; nt++) {
            int col = bn + wn + nt * 8 + tg * 2;
            float b0 = bo[col], b1 = bo[col + 1];
            #pragma unroll
            for (int half = 0; half < 2; half++) {
                int row = bm + wm + mt * 16 + g + half * 8;
                float* p = &out[(size_t)row * DOUT + col];
                p[0] = c[mt * 4 + nt][half * 2 + 0] + b0;
                p[1] = c[mt * 4 + nt][half * 2 + 1] + b1;
            }
        }
    }
}

// ---------------------------------------------------------------------------
// Tensor-core flash attention = R12 form (best known) + two structural
// changes:
//  (a) P-exchange barrier is PAIR-SCOPED: P rows are warp-private; only
//      columns cross between the 2 warps sharing wm -> bar.sync(pair,64)
//      replaces the block-wide sync between S-phase and PV-phase.
//  (b) Fully-masked-pair skip: on the last K-tile, pairs whose rows are all
//      < k0 (all causal-masked, P==0) skip S-MMA/P/PV entirely (their P rows
//      are read only by themselves). Condition is pair-uniform.
// Block-wide syncs kept: after K/V load, and at loop end (K/V overwrite +
// Ls visibility for the epilogue).
// NOTE: the Ks fragment read MUST stay transposed (Ks[col*68 + kk+tg]) —
// for S = Q K^T the MMA reduction dim is d, keys are the n dim.
// ---------------------------------------------------------------------------
#define QS_OFF 0
#define KS_OFF (128*68)
#define VS_OFF (KS_OFF + 64*68)
#define PS_OFF (VS_OFF + 64*68)
#define RS_OFF (PS_OFF + 128*68)
#define LS_OFF (RS_OFF + 2048)
#define ATTN_SMEM_FLOATS (LS_OFF + 128)
#define ATTN_SMEM_BYTES (ATTN_SMEM_FLOATS * 4)

__global__ __launch_bounds__(256, 2) void attn_tc(
    const float* __restrict__ wp,
    const float* __restrict__ vp)
{
    extern __shared__ float sm[];
    unsigned* Qs = (unsigned*)sm + QS_OFF;
    unsigned* Ks = (unsigned*)sm + KS_OFF;
    unsigned* Vs = (unsigned*)sm + VS_OFF;
    unsigned* Ps = (unsigned*)sm + PS_OFF;
    float*    Rs = sm + RS_OFF;
    float*    Ls = sm + LS_OFF;

    const int qb  = (NN / 128 - 1) - blockIdx.x;   // largest-first
    const int h   = blockIdx.y;
    const int b   = blockIdx.z;
    const int tid = threadIdx.x;
    const int warp = tid >> 5;
    const int lane = tid & 31;
    const int g  = lane >> 2;
    const int tg = lane & 3;
    const int wm = (warp >> 1) * 32;
    const int wn = (warp & 1) * 32;
    const int pair_bar = (warp >> 1) + 1;   // named barrier id 1..4

    const size_t head_off = (size_t)(b * HH + h) * NN * HD;
    const float* qbase = g_q + head_off;
    const float* kbase = g_k + head_off;
    const float* vbase = g_v + head_off;

    const float wh = wp[h];
    const float vh = vp[h];
    const float c1 = 1.f + __expf(vh);

    for (int i = tid; i < NN; i += 256)
        Rs[i] = c1 / (1.f + __expf(vh - wh * (float)i)) * 0.125f;
    if (tid < 128) Ls[tid] = 0.f;

    #pragma unroll
    for (int s = 0; s < 8; s++) {
        int slot = tid + s * 256;
        int r  = slot >> 4;
        int c4 = (slot & 15) << 2;
        float4 v = *(const float4*)&qbase[(size_t)(qb * 128 + r) * HD + c4];
        uint4 u = { f2tf32(v.x), f2tf32(v.y), f2tf32(v.z), f2tf32(v.w) };
        *(uint4*)&Qs[r * 68 + c4] = u;
    }
    __syncthreads();

    float co[2][4][4];
    #pragma unroll
    for (int mt = 0; mt < 2; mt++)
        #pragma unroll
        for (int nt = 0; nt < 4; nt++)
            #pragma unroll
            for (int i = 0; i < 4; i++) co[mt][nt][i] = 0.f;

    const int ktmax = (qb + 1) * 2;
    for (int kt = 0; kt < ktmax; kt++) {
        const int k0 = kt * 64;

        #pragma unroll
        for (int s = 0; s < 4; s++) {
            int slot = tid + s * 256;
            int r  = slot >> 4;
            int c4 = (slot & 15) << 2;
            float4 kv = *(const float4*)&kbase[(size_t)(k0 + r) * HD + c4];
            float4 vv = *(const float4*)&vbase[(size_t)(k0 + r) * HD + c4];
            uint4 ku = { f2tf32(kv.x), f2tf32(kv.y), f2tf32(kv.z), f2tf32(kv.w) };
            uint4 vu = { f2tf32(vv.x), f2tf32(vv.y), f2tf32(vv.z), f2tf32(vv.w) };
            *(uint4*)&Ks[r * 68 + c4] = ku;
            *(uint4*)&Vs[r * 68 + c4] = vu;
        }
        __syncthreads();

        // Pair fully masked? (all rows wm..wm+31 < k0 in causal terms)
        const bool active = (qb * 128 + wm + 31) >= k0;

        if (active) {
            float cs[2][4][4];
            #pragma unroll
            for (int mt = 0; mt < 2; mt++)
                #pragma unroll
                for (int nt = 0; nt < 4; nt++)
                    #pragma unroll
                    for (int i = 0; i < 4; i++) cs[mt][nt][i] = 0.f;

            #pragma unroll
            for (int kk = 0; kk < 64; kk += 8) {
                unsigned a[2][4], bb[4][2];
                #pragma unroll
                for (int mt = 0; mt < 2; mt++) {
                    int row = wm + mt * 16 + g;
                    a[mt][0] = Qs[row * 68 + kk + tg];
                    a[mt][1] = Qs[(row + 8) * 68 + kk + tg];
                    a[mt][2] = Qs[row * 68 + kk + tg + 4];
                    a[mt][3] = Qs[(row + 8) * 68 + kk + tg + 4];
                }
                #pragma unroll
                for (int nt = 0; nt < 4; nt++) {
                    int col = wn + nt * 8 + g;   // key index within tile
                    bb[nt][0] = Ks[col * 68 + kk + tg    ];
                    bb[nt][1] = Ks[col * 68 + kk + tg + 4];
                }
                #pragma unroll
                for (int mt = 0; mt < 2; mt++)
                    #pragma unroll
                    for (int nt = 0; nt < 4; nt++)
                        mma_tf32(cs[mt][nt],
                                 a[mt][0], a[mt][1], a[mt][2], a[mt][3],
                                 bb[nt][0], bb[nt][1]);
            }

            float rp[2][2] = {{0.f, 0.f}, {0.f, 0.f}};
            #pragma unroll
            for (int mt = 0; mt < 2; mt++) {
                #pragma unroll
                for (int nt = 0; nt < 4; nt++) {
                    #pragma unroll
                    for (int i = 0; i < 4; i++) {
                        int half = i >> 1;
                        int row_l = wm + mt * 16 + g + half * 8;
                        int col = wn + nt * 8 + tg * 2 + (i & 1);
                        int R = (qb * 128 + row_l) - (k0 + col);
                        float s = fmaxf(cs[mt][nt][i], 0.f);
                        float p = (R >= 0) ? __expf(s * Rs[R]) : 0.f;
                        unsigned pt = f2tf32(p);
                        Ps[row_l * 68 + col] = pt;
                        rp[mt][half] += __uint_as_float(pt);
                    }
                }
            }
            #pragma unroll
            for (int mt = 0; mt < 2; mt++)
                #pragma unroll
                for (int half = 0; half < 2; half++) {
                    float v = rp[mt][half];
                    v += __shfl_xor_sync(0xffffffff, v, 1);
                    v += __shfl_xor_sync(0xffffffff, v, 2);
                    if (tg == 0)
                        atomicAdd(&Ls[wm + mt * 16 + g + half * 8], v);
                }

            // Pair-scoped barrier: exchange P columns within the wm-pair.
            asm volatile("bar.sync %0, 64;" :: "r"(pair_bar) : "memory");

            #pragma unroll
            for (int kk = 0; kk < 64; kk += 8) {
                unsigned pa[2][4], bb[4][2];
                #pragma unroll
                for (int mt = 0; mt < 2; mt++) {
                    int row = wm + mt * 16 + g;
                    pa[mt][0] = Ps[row * 68 + kk + tg];
                    pa[mt][1] = Ps[(row + 8) * 68 + kk + tg];
                    pa[mt][2] = Ps[row * 68 + kk + tg + 4];
                    pa[mt][3] = Ps[(row + 8) * 68 + kk + tg + 4];
                }
                #pragma unroll
                for (int nt = 0; nt < 4; nt++) {
                    int col = wn + nt * 8 + g;   // d index
                    bb[nt][0] = Vs[(kk + tg) * 68 + col];
                    bb[nt][1] = Vs[(kk + tg + 4) * 68 + col];
                }
                #pragma unroll
                for (int mt = 0; mt < 2; mt++)
                    #pragma unroll
                    for (int nt = 0; nt < 4; nt++)
                        mma_tf32(co[mt][nt],
                                 pa[mt][0], pa[mt][1], pa[mt][2], pa[mt][3],
                                 bb[nt][0], bb[nt][1]);
            }
        }
        __syncthreads();
    }

    #pragma unroll
    for (int mt = 0; mt < 2; mt++) {
        #pragma unroll
        for (int half = 0; half < 2; half++) {
            int row_l = wm + mt * 16 + g + half * 8;
            float inv = 1.f / Ls[row_l];
            int n_ = qb * 128 + row_l;
            float* op = g_ctx + ((size_t)(b * NN + n_) * DOUT) + h * HD;
            #pragma unroll
            for (int nt = 0; nt < 4; nt++) {
                int col = wn + nt * 8 + tg * 2;
                op[col]     = co[mt][nt][half * 2 + 0] * inv;
                op[col + 1] = co[mt][nt][half * 2 + 1] * inv;
            }
        }
    }
}

// ---------------------------------------------------------------------------
extern "C" void kernel_launch(void* const* d_in, const int* in_sizes, int n_in,
                              void* d_out, int out_size)
{
    const float* x  = (const float*)d_in[0];
    const float* Wq = (const float*)d_in[1];
    const float* Wk = (const float*)d_in[2];
    const float* Wv = (const float*)d_in[3];
    const float* Wo = (const float*)d_in[4];
    const float* bo = (const float*)d_in[5];
    const float* w  = (const float*)d_in[6];
    const float* v  = (const float*)d_in[7];
    float* out = (float*)d_out;

    cudaFuncSetAttribute(attn_tc,
        cudaFuncAttributeMaxDynamicSharedMemorySize, ATTN_SMEM_BYTES);

    dim3 g1(DOUT / 128, (BB * NN) / 128, 3);
    qkv_gemm_tc<<<g1, 256>>>(x, Wq, Wk, Wv);

    dim3 g2(NN / 128, HH, BB);
    attn_tc<<<g2, 256, ATTN_SMEM_BYTES>>>(w, v);

    dim3 g3(DOUT / 128, (BB * NN) / 128, 1);
    out_gemm_tc<<<g3, 256>>>(Wo, bo, out);
}